// round 15
// baseline (speedup 1.0000x reference)
#include <cuda_runtime.h>
#include <cuda_fp16.h>
#include <math.h>
#include <math_constants.h>
#include <stdint.h>

// ---------------- problem constants ----------------
#define B_    4
#define T_    1024
#define DM    2048
#define HD    64
#define NH    32
#define NKV   8
#define QMULT 4
#define WIN   128
#define QKVD  3072           // 64*(32+16)
#define SM_SCALE 0.125f      // 1/sqrt(64)
#define NTOK  (B_*T_)        // 4096

// ---------------- scratch (no allocs allowed) ----------------
__device__ float  g_qkv  [NTOK * QKVD];  // 50.3 MB  qkv projection output (fp32, un-roped)
__device__ __half g_xh   [NTOK * DM];    // 16.8 MB  x -> fp16
__device__ __half g_qwh  [QKVD * DM];    // 12.6 MB  qkv_w -> fp16
__device__ __half g_owh  [DM * DM];      //  8.4 MB  out_w -> fp16
__device__ __half g_attnh[NTOK * DM];    // 16.8 MB  attn output (fp16)
__device__ float  g_cos  [T_ * 32];
__device__ float  g_sin  [T_ * 32];

// ---------------- PTX helpers ----------------
__device__ __forceinline__ uint32_t smem_u32(const void* p) {
    uint32_t a;
    asm("{ .reg .u64 t; cvta.to.shared.u64 t, %1; cvt.u32.u64 %0, t; }" : "=r"(a) : "l"(p));
    return a;
}
__device__ __forceinline__ void cp16(uint32_t dst, const void* src) {
    asm volatile("cp.async.cg.shared.global [%0], [%1], 16;" :: "r"(dst), "l"(src));
}
__device__ __forceinline__ void ldsm_x4(uint32_t& r0, uint32_t& r1, uint32_t& r2, uint32_t& r3, uint32_t addr) {
    asm volatile("ldmatrix.sync.aligned.m8n8.x4.shared.b16 {%0,%1,%2,%3}, [%4];"
        : "=r"(r0), "=r"(r1), "=r"(r2), "=r"(r3) : "r"(addr));
}
__device__ __forceinline__ void mma_f16(float* c, const uint32_t* a, const uint32_t* b) {
    asm volatile("mma.sync.aligned.m16n8k16.row.col.f32.f16.f16.f32 "
        "{%0,%1,%2,%3}, {%4,%5,%6,%7}, {%8,%9}, {%0,%1,%2,%3};"
        : "+f"(c[0]), "+f"(c[1]), "+f"(c[2]), "+f"(c[3])
        : "r"(a[0]), "r"(a[1]), "r"(a[2]), "r"(a[3]), "r"(b[0]), "r"(b[1]));
}

// ---------------- rope tables (YaRN / NTK-by-parts) ----------------
__global__ void rope_table_kernel(float* __restrict__ cost, float* __restrict__ sint) {
    int t = blockIdx.x;
    int d = threadIdx.x;
    const double theta = 150000.0;
    const double two_pi = 6.283185307179586476925286766559;
    double freq = pow(theta, (double)d / 32.0);
    double concentration = 0.1 * log(32.0) + 1.0;
    double lt = log(theta);
    double low  = 32.0 * log(1024.0 / (32.0 * two_pi)) / lt;
    double high = 32.0 * log(1024.0 / (1.0  * two_pi)) / lt;
    double interpolation = 1.0 / (32.0 * freq);
    double extrapolation = 1.0 / freq;
    double ramp = ((double)d - low) / (high - low);
    ramp = fmin(fmax(ramp, 0.0), 1.0);
    double inv_freq = interpolation * ramp + extrapolation * (1.0 - ramp);
    double a = (double)t * inv_freq;
    cost[t * 32 + d] = (float)(cos(a) * concentration);
    sint[t * 32 + d] = (float)(sin(a) * concentration);
}

// ---------------- fused fp32 -> fp16 conversion (x, qkv_w, out_w in one grid) ----------------
#define N4X (NTOK * DM / 4)      // 2097152
#define N4Q (QKVD * DM / 4)      // 1572864
#define N4O (DM * DM / 4)        // 1048576
__global__ void f16_convert_all_kernel(const float* __restrict__ x, __half* __restrict__ xh,
                                       const float* __restrict__ qw, __half* __restrict__ qwh,
                                       const float* __restrict__ ow, __half* __restrict__ owh) {
    int i = blockIdx.x * blockDim.x + threadIdx.x;
    const float* in; __half* out; int k;
    if (i < N4X)                { in = x;  out = xh;  k = i; }
    else if (i < N4X + N4Q)     { in = qw; out = qwh; k = i - N4X; }
    else if (i < N4X + N4Q + N4O) { in = ow; out = owh; k = i - N4X - N4Q; }
    else return;
    float4 v = ((const float4*)in)[k];
    __half2* o2 = (__half2*)out;
    o2[2 * k]     = __floats2half2_rn(v.x, v.y);
    o2[2 * k + 1] = __floats2half2_rn(v.z, v.w);
}

// ---------------- fp16 tensor-core GEMM: C[M,N] = A[M,K] @ B[N,K]^T + bias ----------------
// 128x256 CTA tile, BK=64, SW128 swizzle, 4-stage cp.async pipeline (wait_group 2),
// single syncthreads per K-iter, 8 warps each 64x64 via m16n8k16, fp32 accum,
// ks-level fragment double-buffering. (R10 config — measured best.)
#define BM 128
#define BN 256
#define BK 64
#define A_STAGE 16384                 // 128 rows * 128B
#define B_STAGE 32768                 // 256 rows * 128B
#define STAGE_BYTES (A_STAGE + B_STAGE)
#define NSTAGE 4

__global__ __launch_bounds__(256, 1) void gemm_f16_nt_bias(
    const __half* __restrict__ A, const __half* __restrict__ Bw,
    const float* __restrict__ bias, float* __restrict__ C,
    int M, int N, int K)
{
    extern __shared__ char dsm[];
    const uint32_t dynbase = smem_u32(dsm);
    const uint32_t base    = (dynbase + 1023u) & ~1023u;

    const int tid  = threadIdx.x;
    const int lane = tid & 31;
    const int wid  = tid >> 5;
    const int wm   = wid >> 2;          // 0..1 -> m base wm*64
    const int wn   = wid & 3;           // 0..3 -> n base wn*64
    const int bm   = blockIdx.y * BM;
    const int bn   = blockIdx.x * BN;

    float acc[4][8][4];
    #pragma unroll
    for (int i = 0; i < 4; i++)
        #pragma unroll
        for (int j = 0; j < 8; j++)
            #pragma unroll
            for (int r = 0; r < 4; r++) acc[i][j][r] = 0.0f;

    const int kIter = K / BK;

    auto load_stage = [&](int buf, int t) {
        const uint32_t aS = base + buf * STAGE_BYTES;
        const uint32_t bS = aS + A_STAGE;
        const __half* Ab = A  + (size_t)bm * K + (size_t)t * BK;
        const __half* Bb = Bw + (size_t)bn * K + (size_t)t * BK;
        #pragma unroll
        for (int j = 0; j < 4; j++) {
            int f = tid + 256 * j;
            int r = f >> 3, c = f & 7;
            uint32_t off = (uint32_t)(r * 128 + c * 16);
            uint32_t sw  = off ^ ((off >> 3) & 0x70);
            cp16(aS + sw, Ab + (size_t)r * K + c * 8);
        }
        #pragma unroll
        for (int j = 0; j < 8; j++) {
            int f = tid + 256 * j;
            int r = f >> 3, c = f & 7;
            uint32_t off = (uint32_t)(r * 128 + c * 16);
            uint32_t sw  = off ^ ((off >> 3) & 0x70);
            cp16(bS + sw, Bb + (size_t)r * K + c * 8);
        }
    };

    load_stage(0, 0);
    asm volatile("cp.async.commit_group;");
    load_stage(1, 1);
    asm volatile("cp.async.commit_group;");
    load_stage(2, 2);
    asm volatile("cp.async.commit_group;");

    const int rsel = lane & 15;
    const int hsel = (lane >> 4) & 1;

    uint32_t af[2][4][4];
    uint32_t bf[2][8][2];

    auto load_frags = [&](uint32_t aS, uint32_t bS, int ks,
                          uint32_t (&a)[4][4], uint32_t (&b)[8][2]) {
        #pragma unroll
        for (int mt = 0; mt < 4; mt++) {
            int row = wm * 64 + mt * 16 + rsel;
            uint32_t off = (uint32_t)(row * 128 + ks * 32 + hsel * 16);
            uint32_t sw  = off ^ ((off >> 3) & 0x70);
            ldsm_x4(a[mt][0], a[mt][1], a[mt][2], a[mt][3], aS + sw);
        }
        #pragma unroll
        for (int np = 0; np < 4; np++) {
            int row = wn * 64 + np * 16 + rsel;
            uint32_t off = (uint32_t)(row * 128 + ks * 32 + hsel * 16);
            uint32_t sw  = off ^ ((off >> 3) & 0x70);
            uint32_t q0, q1, q2, q3;
            ldsm_x4(q0, q1, q2, q3, bS + sw);
            b[2 * np][0]     = q0; b[2 * np][1]     = q2;
            b[2 * np + 1][0] = q1; b[2 * np + 1][1] = q3;
        }
    };

    for (int t = 0; t < kIter; t++) {
        asm volatile("cp.async.wait_group 2;");
        __syncthreads();

        const uint32_t aS = base + (t & 3) * STAGE_BYTES;
        const uint32_t bS = aS + A_STAGE;

        load_frags(aS, bS, 0, af[0], bf[0]);

        if (t + 3 < kIter) load_stage((t + 3) & 3, t + 3);
        asm volatile("cp.async.commit_group;");

        #pragma unroll
        for (int ks = 0; ks < 4; ks++) {
            const int cur = ks & 1;
            if (ks < 3) load_frags(aS, bS, ks + 1, af[cur ^ 1], bf[cur ^ 1]);
            #pragma unroll
            for (int mt = 0; mt < 4; mt++)
                #pragma unroll
                for (int nt = 0; nt < 8; nt++)
                    mma_f16(acc[mt][nt], af[cur][mt], bf[cur][nt]);
        }
    }

    const int cx = (lane & 3) * 2;
    const int cy = lane >> 2;
    #pragma unroll
    for (int nt = 0; nt < 8; nt++) {
        const int c0 = bn + wn * 64 + nt * 8 + cx;
        const float bv0 = bias[c0];
        const float bv1 = bias[c0 + 1];
        #pragma unroll
        for (int mt = 0; mt < 4; mt++) {
            const int r0 = bm + wm * 64 + mt * 16 + cy;
            *(float2*)(C + (size_t)r0 * N + c0)       = make_float2(acc[mt][nt][0] + bv0, acc[mt][nt][1] + bv1);
            *(float2*)(C + (size_t)(r0 + 8) * N + c0) = make_float2(acc[mt][nt][2] + bv0, acc[mt][nt][3] + bv1);
        }
    }
}

// ---------------- attention: sliding-window causal GQA with sink + fused RoPE ----------------
// block 512 = 4 q-heads x 64 queries x 2 dim-halves; warp-local 143-iter window
// (warp-uniform smem rows -> broadcast LDS). K,V both fp32 float4 loads.
__global__ __launch_bounds__(512) void attn_kernel(
    const float* __restrict__ qkv, const float* __restrict__ sinks,
    const float* __restrict__ cost, const float* __restrict__ sint,
    __half* __restrict__ out)
{
    extern __shared__ float smem[];
    float* Ks = smem;                 // 191*64 f32
    float* Vs = smem + 191 * 64;      // 191*64 f32

    const int qb = blockIdx.x;
    const int kv = blockIdx.y;
    const int b  = blockIdx.z;
    const int tid = threadIdx.x;

    const int qstart = qb * 64;
    const int j0 = qstart - (WIN - 1);

    // K tile with fused rope
    for (int idx = tid; idx < 191 * 8; idx += 512) {
        int row = idx >> 3;
        int c   = (idx & 7) << 2;
        int j   = j0 + row;
        float4 r1 = make_float4(0.f, 0.f, 0.f, 0.f);
        float4 r2 = make_float4(0.f, 0.f, 0.f, 0.f);
        if (j >= 0) {
            const float* kb = qkv + (size_t)(b * T_ + j) * QKVD + 2048 + kv * 64;
            float4 x1 = *(const float4*)(kb + c);
            float4 x2 = *(const float4*)(kb + c + 32);
            float4 cc = *(const float4*)(cost + j * 32 + c);
            float4 ss = *(const float4*)(sint + j * 32 + c);
            r1.x = x1.x * cc.x - x2.x * ss.x;  r2.x = x2.x * cc.x + x1.x * ss.x;
            r1.y = x1.y * cc.y - x2.y * ss.y;  r2.y = x2.y * cc.y + x1.y * ss.y;
            r1.z = x1.z * cc.z - x2.z * ss.z;  r2.z = x2.z * cc.z + x1.z * ss.z;
            r1.w = x1.w * cc.w - x2.w * ss.w;  r2.w = x2.w * cc.w + x1.w * ss.w;
        }
        *(float4*)(Ks + row * 64 + c)      = r1;
        *(float4*)(Ks + row * 64 + c + 32) = r2;
    }
    // V tile (fp32)
    for (int idx = tid; idx < 191 * 16; idx += 512) {
        int row = idx >> 4;
        int c   = (idx & 15) << 2;
        int j   = j0 + row;
        float4 vv4 = make_float4(0.f, 0.f, 0.f, 0.f);
        if (j >= 0) {
            const float* base = qkv + (size_t)(b * T_ + j) * QKVD;
            vv4 = *(const float4*)(base + 2560 + kv * 64 + c);
        }
        *(float4*)(Vs + row * 64 + c) = vv4;
    }

    const int half = tid & 1;            // which 32-dim half this thread owns
    const int qi   = (tid >> 1) & 63;
    const int qh   = tid >> 7;           // 0..3
    const int h    = kv * QMULT + qh;
    const int i    = qstart + qi;
    const int wq0  = ((tid >> 5) & 3) * 16;   // warp's base query within block

    // Q load with fused rope: thread owns dims [half*32, half*32+32)
    float qv[32];
    {
        const float* qp = qkv + (size_t)(b * T_ + i) * QKVD + h * 64;
        #pragma unroll
        for (int d = 0; d < 32; d += 4) {
            float4 x1 = *(const float4*)(qp + d);
            float4 x2 = *(const float4*)(qp + d + 32);
            float4 cc = *(const float4*)(cost + i * 32 + d);
            float4 ss = *(const float4*)(sint + i * 32 + d);
            if (half == 0) {
                qv[d + 0] = x1.x * cc.x - x2.x * ss.x;
                qv[d + 1] = x1.y * cc.y - x2.y * ss.y;
                qv[d + 2] = x1.z * cc.z - x2.z * ss.z;
                qv[d + 3] = x1.w * cc.w - x2.w * ss.w;
            } else {
                qv[d + 0] = x2.x * cc.x + x1.x * ss.x;
                qv[d + 1] = x2.y * cc.y + x1.y * ss.y;
                qv[d + 2] = x2.z * cc.z + x1.z * ss.z;
                qv[d + 3] = x2.w * cc.w + x1.w * ss.w;
            }
        }
    }
    const int dbase = half * 32;

    __syncthreads();

    float m = -CUDART_INF_F;
    float l = 0.0f;
    float o[32];
    #pragma unroll
    for (int d = 0; d < 32; d++) o[d] = 0.0f;

    // warp covers queries [wq0, wq0+15] -> union of valid keys = [wq0, wq0+142]
    for (int w = 0; w < 143; w++) {
        int jr = wq0 + w;
        int j  = j0 + jr;
        const float* kr = Ks + jr * 64 + dbase;
        float s0 = 0.f, s1 = 0.f, s2 = 0.f, s3 = 0.f;
        #pragma unroll
        for (int d = 0; d < 32; d += 4) {
            float4 k4 = *(const float4*)(kr + d);
            s0 = fmaf(qv[d + 0], k4.x, s0);
            s1 = fmaf(qv[d + 1], k4.y, s1);
            s2 = fmaf(qv[d + 2], k4.z, s2);
            s3 = fmaf(qv[d + 3], k4.w, s3);
        }
        float part = (s0 + s1) + (s2 + s3);
        float s = (part + __shfl_xor_sync(0xffffffffu, part, 1)) * SM_SCALE;

        bool valid = (jr >= qi) && (jr <= qi + (WIN - 1)) && (j >= 0);
        if (valid) {
            if (s > m) {
                float corr = __expf(m - s);
                l *= corr;
                #pragma unroll
                for (int d = 0; d < 32; d++) o[d] *= corr;
                m = s;
            }
            float p = __expf(s - m);
            l += p;
            const float* vr = Vs + jr * 64 + dbase;
            #pragma unroll
            for (int d = 0; d < 32; d += 4) {
                float4 v4 = *(const float4*)(vr + d);
                o[d + 0] = fmaf(p, v4.x, o[d + 0]);
                o[d + 1] = fmaf(p, v4.y, o[d + 1]);
                o[d + 2] = fmaf(p, v4.z, o[d + 2]);
                o[d + 3] = fmaf(p, v4.w, o[d + 3]);
            }
        }
    }

    float denom = l + __expf(sinks[h] - m);
    float inv = 1.0f / denom;
    __half2* op = (__half2*)(out + (size_t)(b * T_ + i) * DM + h * 64 + dbase);
    #pragma unroll
    for (int d = 0; d < 32; d += 2)
        op[d >> 1] = __floats2half2_rn(o[d] * inv, o[d + 1] * inv);
}

// ---------------- launch ----------------
extern "C" void kernel_launch(void* const* d_in, const int* in_sizes, int n_in,
                              void* d_out, int out_size) {
    const float* x      = (const float*)d_in[0];
    const float* qkv_w  = (const float*)d_in[1];
    const float* qkv_b  = (const float*)d_in[2];
    const float* out_w  = (const float*)d_in[3];
    const float* out_b  = (const float*)d_in[4];
    const float* sinks  = (const float*)d_in[5];
    float* out = (float*)d_out;

    float *qkv, *cosp, *sinp;
    __half *xh, *qwh, *owh, *attnh;
    cudaGetSymbolAddress((void**)&qkv,   g_qkv);
    cudaGetSymbolAddress((void**)&xh,    g_xh);
    cudaGetSymbolAddress((void**)&qwh,   g_qwh);
    cudaGetSymbolAddress((void**)&owh,   g_owh);
    cudaGetSymbolAddress((void**)&attnh, g_attnh);
    cudaGetSymbolAddress((void**)&cosp,  g_cos);
    cudaGetSymbolAddress((void**)&sinp,  g_sin);

    const int gemmSmem = NSTAGE * STAGE_BYTES + 1024;   // 197632
    const int attnSmem = 191 * 64 * 2 * sizeof(float);  // 97792
    cudaFuncSetAttribute(gemm_f16_nt_bias, cudaFuncAttributeMaxDynamicSharedMemorySize, gemmSmem);
    cudaFuncSetAttribute(attn_kernel, cudaFuncAttributeMaxDynamicSharedMemorySize, attnSmem);

    // 1. rope tables
    rope_table_kernel<<<T_, 32>>>(cosp, sinp);

    // 2. fused fp16 conversion pass (x, qkv_w, out_w)
    {
        int total = N4X + N4Q + N4O;
        f16_convert_all_kernel<<<(total + 255) / 256, 256>>>(x, xh, qkv_w, qwh, out_w, owh);
    }

    // 3. QKV projection: [4096,3072] = x @ qkv_w^T + b   (fp16 mma)
    {
        dim3 grid(QKVD / BN, NTOK / BM);   // (12, 32)
        gemm_f16_nt_bias<<<grid, 256, gemmSmem>>>(xh, qwh, qkv_b, qkv, NTOK, QKVD, DM);
    }

    // 4. attention with fused rope (fp16 output)
    {
        dim3 grid(T_ / 64, NKV, B_);
        attn_kernel<<<grid, 512, attnSmem>>>(qkv, sinks, cosp, sinp, attnh);
    }

    // 5. output projection: [4096,2048] = attn @ out_w^T + b  (fp16 mma)
    {
        dim3 grid(DM / BN, NTOK / BM);     // (8, 32)
        gemm_f16_nt_bias<<<grid, 256, gemmSmem>>>(attnh, owh, out_b, out, NTOK, DM, DM);
    }
}

// round 16
// speedup vs baseline: 1.6968x; 1.6968x over previous
#include <cuda_runtime.h>
#include <cuda_fp16.h>
#include <math.h>
#include <math_constants.h>
#include <stdint.h>

// ---------------- problem constants ----------------
#define B_    4
#define T_    1024
#define DM    2048
#define HD    64
#define NH    32
#define NKV   8
#define QMULT 4
#define WIN   128
#define QKVD  3072           // 64*(32+16)
#define SM_SCALE 0.125f      // 1/sqrt(64)
#define NTOK  (B_*T_)        // 4096
#define SMASK (-1e30f)

// ---------------- scratch (no allocs allowed) ----------------
__device__ float  g_qkv  [NTOK * QKVD];  // 50.3 MB  qkv projection output (fp32, un-roped)
__device__ __half g_xh   [NTOK * DM];    // 16.8 MB  x -> fp16
__device__ __half g_qwh  [QKVD * DM];    // 12.6 MB  qkv_w -> fp16
__device__ __half g_owh  [DM * DM];      //  8.4 MB  out_w -> fp16
__device__ __half g_attnh[NTOK * DM];    // 16.8 MB  attn output (fp16)
__device__ float  g_cos  [T_ * 32];
__device__ float  g_sin  [T_ * 32];

// ---------------- PTX helpers ----------------
__device__ __forceinline__ uint32_t smem_u32(const void* p) {
    uint32_t a;
    asm("{ .reg .u64 t; cvta.to.shared.u64 t, %1; cvt.u32.u64 %0, t; }" : "=r"(a) : "l"(p));
    return a;
}
__device__ __forceinline__ void cp16(uint32_t dst, const void* src) {
    asm volatile("cp.async.cg.shared.global [%0], [%1], 16;" :: "r"(dst), "l"(src));
}
__device__ __forceinline__ void ldsm_x4(uint32_t& r0, uint32_t& r1, uint32_t& r2, uint32_t& r3, uint32_t addr) {
    asm volatile("ldmatrix.sync.aligned.m8n8.x4.shared.b16 {%0,%1,%2,%3}, [%4];"
        : "=r"(r0), "=r"(r1), "=r"(r2), "=r"(r3) : "r"(addr));
}
__device__ __forceinline__ void ldsm_x4_trans(uint32_t& r0, uint32_t& r1, uint32_t& r2, uint32_t& r3, uint32_t addr) {
    asm volatile("ldmatrix.sync.aligned.m8n8.x4.trans.shared.b16 {%0,%1,%2,%3}, [%4];"
        : "=r"(r0), "=r"(r1), "=r"(r2), "=r"(r3) : "r"(addr));
}
__device__ __forceinline__ void mma_f16(float* c, const uint32_t* a, const uint32_t* b) {
    asm volatile("mma.sync.aligned.m16n8k16.row.col.f32.f16.f16.f32 "
        "{%0,%1,%2,%3}, {%4,%5,%6,%7}, {%8,%9}, {%0,%1,%2,%3};"
        : "+f"(c[0]), "+f"(c[1]), "+f"(c[2]), "+f"(c[3])
        : "r"(a[0]), "r"(a[1]), "r"(a[2]), "r"(a[3]), "r"(b[0]), "r"(b[1]));
}
__device__ __forceinline__ uint32_t packh2(float a, float b) {
    __half2 h = __floats2half2_rn(a, b);
    return *(uint32_t*)&h;
}
__device__ __forceinline__ uint32_t swz(uint32_t off) { return off ^ ((off >> 3) & 0x70); }

// ---------------- rope tables (YaRN / NTK-by-parts) ----------------
__global__ void rope_table_kernel(float* __restrict__ cost, float* __restrict__ sint) {
    int t = blockIdx.x;
    int d = threadIdx.x;
    const double theta = 150000.0;
    const double two_pi = 6.283185307179586476925286766559;
    double freq = pow(theta, (double)d / 32.0);
    double concentration = 0.1 * log(32.0) + 1.0;
    double lt = log(theta);
    double low  = 32.0 * log(1024.0 / (32.0 * two_pi)) / lt;
    double high = 32.0 * log(1024.0 / (1.0  * two_pi)) / lt;
    double interpolation = 1.0 / (32.0 * freq);
    double extrapolation = 1.0 / freq;
    double ramp = ((double)d - low) / (high - low);
    ramp = fmin(fmax(ramp, 0.0), 1.0);
    double inv_freq = interpolation * ramp + extrapolation * (1.0 - ramp);
    double a = (double)t * inv_freq;
    cost[t * 32 + d] = (float)(cos(a) * concentration);
    sint[t * 32 + d] = (float)(sin(a) * concentration);
}

// ---------------- fused fp32 -> fp16 conversion (x, qkv_w, out_w in one grid) ----------------
#define N4X (NTOK * DM / 4)      // 2097152
#define N4Q (QKVD * DM / 4)      // 1572864
#define N4O (DM * DM / 4)        // 1048576
__global__ void f16_convert_all_kernel(const float* __restrict__ x, __half* __restrict__ xh,
                                       const float* __restrict__ qw, __half* __restrict__ qwh,
                                       const float* __restrict__ ow, __half* __restrict__ owh) {
    int i = blockIdx.x * blockDim.x + threadIdx.x;
    const float* in; __half* out; int k;
    if (i < N4X)                { in = x;  out = xh;  k = i; }
    else if (i < N4X + N4Q)     { in = qw; out = qwh; k = i - N4X; }
    else if (i < N4X + N4Q + N4O) { in = ow; out = owh; k = i - N4X - N4Q; }
    else return;
    float4 v = ((const float4*)in)[k];
    __half2* o2 = (__half2*)out;
    o2[2 * k]     = __floats2half2_rn(v.x, v.y);
    o2[2 * k + 1] = __floats2half2_rn(v.z, v.w);
}

// ---------------- fp16 tensor-core GEMM: C[M,N] = A[M,K] @ B[N,K]^T + bias ----------------
// (R10 config — measured best. Unchanged.)
#define BM 128
#define BN 256
#define BK 64
#define A_STAGE 16384
#define B_STAGE 32768
#define STAGE_BYTES (A_STAGE + B_STAGE)
#define NSTAGE 4

__global__ __launch_bounds__(256, 1) void gemm_f16_nt_bias(
    const __half* __restrict__ A, const __half* __restrict__ Bw,
    const float* __restrict__ bias, float* __restrict__ C,
    int M, int N, int K)
{
    extern __shared__ char dsm[];
    const uint32_t dynbase = smem_u32(dsm);
    const uint32_t base    = (dynbase + 1023u) & ~1023u;

    const int tid  = threadIdx.x;
    const int lane = tid & 31;
    const int wid  = tid >> 5;
    const int wm   = wid >> 2;
    const int wn   = wid & 3;
    const int bm   = blockIdx.y * BM;
    const int bn   = blockIdx.x * BN;

    float acc[4][8][4];
    #pragma unroll
    for (int i = 0; i < 4; i++)
        #pragma unroll
        for (int j = 0; j < 8; j++)
            #pragma unroll
            for (int r = 0; r < 4; r++) acc[i][j][r] = 0.0f;

    const int kIter = K / BK;

    auto load_stage = [&](int buf, int t) {
        const uint32_t aS = base + buf * STAGE_BYTES;
        const uint32_t bS = aS + A_STAGE;
        const __half* Ab = A  + (size_t)bm * K + (size_t)t * BK;
        const __half* Bb = Bw + (size_t)bn * K + (size_t)t * BK;
        #pragma unroll
        for (int j = 0; j < 4; j++) {
            int f = tid + 256 * j;
            int r = f >> 3, c = f & 7;
            cp16(aS + swz((uint32_t)(r * 128 + c * 16)), Ab + (size_t)r * K + c * 8);
        }
        #pragma unroll
        for (int j = 0; j < 8; j++) {
            int f = tid + 256 * j;
            int r = f >> 3, c = f & 7;
            cp16(bS + swz((uint32_t)(r * 128 + c * 16)), Bb + (size_t)r * K + c * 8);
        }
    };

    load_stage(0, 0);
    asm volatile("cp.async.commit_group;");
    load_stage(1, 1);
    asm volatile("cp.async.commit_group;");
    load_stage(2, 2);
    asm volatile("cp.async.commit_group;");

    const int rsel = lane & 15;
    const int hsel = (lane >> 4) & 1;

    uint32_t af[2][4][4];
    uint32_t bf[2][8][2];

    auto load_frags = [&](uint32_t aS, uint32_t bS, int ks,
                          uint32_t (&a)[4][4], uint32_t (&b)[8][2]) {
        #pragma unroll
        for (int mt = 0; mt < 4; mt++) {
            int row = wm * 64 + mt * 16 + rsel;
            ldsm_x4(a[mt][0], a[mt][1], a[mt][2], a[mt][3],
                    aS + swz((uint32_t)(row * 128 + ks * 32 + hsel * 16)));
        }
        #pragma unroll
        for (int np = 0; np < 4; np++) {
            int row = wn * 64 + np * 16 + rsel;
            uint32_t q0, q1, q2, q3;
            ldsm_x4(q0, q1, q2, q3, bS + swz((uint32_t)(row * 128 + ks * 32 + hsel * 16)));
            b[2 * np][0]     = q0; b[2 * np][1]     = q2;
            b[2 * np + 1][0] = q1; b[2 * np + 1][1] = q3;
        }
    };

    for (int t = 0; t < kIter; t++) {
        asm volatile("cp.async.wait_group 2;");
        __syncthreads();

        const uint32_t aS = base + (t & 3) * STAGE_BYTES;
        const uint32_t bS = aS + A_STAGE;

        load_frags(aS, bS, 0, af[0], bf[0]);

        if (t + 3 < kIter) load_stage((t + 3) & 3, t + 3);
        asm volatile("cp.async.commit_group;");

        #pragma unroll
        for (int ks = 0; ks < 4; ks++) {
            const int cur = ks & 1;
            if (ks < 3) load_frags(aS, bS, ks + 1, af[cur ^ 1], bf[cur ^ 1]);
            #pragma unroll
            for (int mt = 0; mt < 4; mt++)
                #pragma unroll
                for (int nt = 0; nt < 8; nt++)
                    mma_f16(acc[mt][nt], af[cur][mt], bf[cur][nt]);
        }
    }

    const int cx = (lane & 3) * 2;
    const int cy = lane >> 2;
    #pragma unroll
    for (int nt = 0; nt < 8; nt++) {
        const int c0 = bn + wn * 64 + nt * 8 + cx;
        const float bv0 = bias[c0];
        const float bv1 = bias[c0 + 1];
        #pragma unroll
        for (int mt = 0; mt < 4; mt++) {
            const int r0 = bm + wm * 64 + mt * 16 + cy;
            *(float2*)(C + (size_t)r0 * N + c0)       = make_float2(acc[mt][nt][0] + bv0, acc[mt][nt][1] + bv1);
            *(float2*)(C + (size_t)(r0 + 8) * N + c0) = make_float2(acc[mt][nt][2] + bv0, acc[mt][nt][3] + bv1);
        }
    }
}

// ---------------- MMA flash attention: sliding-window causal GQA with sink + fused RoPE ----
// grid (T/64, NKV, B), 256 threads = 8 warps. Per CTA: 256 query rows (4 heads x 64 queries),
// 192-key tile (window union + 1 pad row). Each warp owns 32 rows; 3 chunks of 64 keys.
// Q/K roped fp16 smem; S = Q@K^T m16n8k16; masked online softmax in acc layout; O += P@V.
#define QS_OFF 0
#define KS_OFF 32768
#define VS_OFF 57344
#define ATTN_SMEM 81920

__global__ __launch_bounds__(256, 1) void attn_mma_kernel(
    const float* __restrict__ qkv, const float* __restrict__ sinks,
    const float* __restrict__ cost, const float* __restrict__ sint,
    __half* __restrict__ out)
{
    extern __shared__ char smraw[];
    const uint32_t sbase = smem_u32(smraw);
    const uint32_t Qs = sbase + QS_OFF;
    const uint32_t Ks = sbase + KS_OFF;
    const uint32_t Vs = sbase + VS_OFF;

    const int qb = blockIdx.x;
    const int kv = blockIdx.y;
    const int b  = blockIdx.z;
    const int tid = threadIdx.x;
    const int lane = tid & 31;
    const int w    = tid >> 5;
    const int g    = lane >> 2;
    const int t4   = lane & 3;
    const int rsel = lane & 15;
    const int hsel = lane >> 4;

    const int qstart = qb * 64;
    const int j0 = qstart - (WIN - 1);

    // ---- Q smem: 256 rows (qh*64+qi) x 64 fp16, roped, swizzled ----
    {
        int r = tid;
        int qh = r >> 6, qi2 = r & 63;
        int itok = qstart + qi2;
        const float* qp = qkv + (size_t)(b * T_ + itok) * QKVD + (kv * QMULT + qh) * 64;
        const float* cr = cost + itok * 32;
        const float* sr = sint + itok * 32;
        #pragma unroll
        for (int c = 0; c < 32; c += 4) {
            float4 x1 = *(const float4*)(qp + c);
            float4 x2 = *(const float4*)(qp + c + 32);
            float4 cc = *(const float4*)(cr + c);
            float4 ss = *(const float4*)(sr + c);
            uint2 lo, hi;
            lo.x = packh2(x1.x * cc.x - x2.x * ss.x, x1.y * cc.y - x2.y * ss.y);
            lo.y = packh2(x1.z * cc.z - x2.z * ss.z, x1.w * cc.w - x2.w * ss.w);
            hi.x = packh2(x2.x * cc.x + x1.x * ss.x, x2.y * cc.y + x1.y * ss.y);
            hi.y = packh2(x2.z * cc.z + x1.z * ss.z, x2.w * cc.w + x1.w * ss.w);
            *(uint2*)(smraw + (QS_OFF + swz((uint32_t)(r * 128 + c * 2))))      = lo;
            *(uint2*)(smraw + (QS_OFF + swz((uint32_t)(r * 128 + 64 + c * 2)))) = hi;
        }
    }
    // ---- K smem: 192 rows x 64 fp16, roped ----
    for (int idx = tid; idx < 192 * 8; idx += 256) {
        int row = idx >> 3;
        int c   = (idx & 7) << 2;
        int j   = j0 + row;
        uint2 lo = {0, 0}, hi = {0, 0};
        if (j >= 0 && j < T_) {
            const float* kb = qkv + (size_t)(b * T_ + j) * QKVD + 2048 + kv * 64;
            float4 x1 = *(const float4*)(kb + c);
            float4 x2 = *(const float4*)(kb + c + 32);
            float4 cc = *(const float4*)(cost + j * 32 + c);
            float4 ss = *(const float4*)(sint + j * 32 + c);
            lo.x = packh2(x1.x * cc.x - x2.x * ss.x, x1.y * cc.y - x2.y * ss.y);
            lo.y = packh2(x1.z * cc.z - x2.z * ss.z, x1.w * cc.w - x2.w * ss.w);
            hi.x = packh2(x2.x * cc.x + x1.x * ss.x, x2.y * cc.y + x1.y * ss.y);
            hi.y = packh2(x2.z * cc.z + x1.z * ss.z, x2.w * cc.w + x1.w * ss.w);
        }
        *(uint2*)(smraw + (KS_OFF + swz((uint32_t)(row * 128 + c * 2))))      = lo;
        *(uint2*)(smraw + (KS_OFF + swz((uint32_t)(row * 128 + 64 + c * 2)))) = hi;
    }
    // ---- V smem: 192 rows x 64 fp16 ----
    for (int idx = tid; idx < 192 * 16; idx += 256) {
        int row = idx >> 4;
        int c   = (idx & 15) << 2;
        int j   = j0 + row;
        uint2 vv = {0, 0};
        if (j >= 0 && j < T_) {
            const float* vb = qkv + (size_t)(b * T_ + j) * QKVD + 2560 + kv * 64 + c;
            float4 v4 = *(const float4*)vb;
            vv.x = packh2(v4.x, v4.y);
            vv.y = packh2(v4.z, v4.w);
        }
        *(uint2*)(smraw + (VS_OFF + swz((uint32_t)(row * 128 + c * 2)))) = vv;
    }

    __syncthreads();

    // ---- resident Q fragments: warp rows [w*32, w*32+32) ----
    uint32_t qa[2][4][4];
    #pragma unroll
    for (int mt = 0; mt < 2; mt++)
        #pragma unroll
        for (int ks = 0; ks < 4; ks++) {
            int row = w * 32 + mt * 16 + rsel;
            ldsm_x4(qa[mt][ks][0], qa[mt][ks][1], qa[mt][ks][2], qa[mt][ks][3],
                    Qs + swz((uint32_t)(row * 128 + ks * 32 + hsel * 16)));
        }

    float oacc[2][8][4];
    #pragma unroll
    for (int mt = 0; mt < 2; mt++)
        #pragma unroll
        for (int nt = 0; nt < 8; nt++)
            #pragma unroll
            for (int c = 0; c < 4; c++) oacc[mt][nt][c] = 0.0f;
    float mrow[2][2] = {{SMASK, SMASK}, {SMASK, SMASK}};
    float lrow[2][2] = {{0.f, 0.f}, {0.f, 0.f}};

    #pragma unroll
    for (int chunk = 0; chunk < 3; chunk++) {
        // ---- S = Q @ K^T for 64 keys ----
        float sacc[2][8][4];
        #pragma unroll
        for (int mt = 0; mt < 2; mt++)
            #pragma unroll
            for (int nt = 0; nt < 8; nt++)
                #pragma unroll
                for (int c = 0; c < 4; c++) sacc[mt][nt][c] = 0.0f;

        #pragma unroll
        for (int ks = 0; ks < 4; ks++) {
            uint32_t kb[8][2];
            #pragma unroll
            for (int np = 0; np < 4; np++) {
                int row = chunk * 64 + np * 16 + rsel;
                uint32_t q0, q1, q2, q3;
                ldsm_x4(q0, q1, q2, q3, Ks + swz((uint32_t)(row * 128 + ks * 32 + hsel * 16)));
                kb[2 * np][0] = q0; kb[2 * np][1] = q2;
                kb[2 * np + 1][0] = q1; kb[2 * np + 1][1] = q3;
            }
            #pragma unroll
            for (int mt = 0; mt < 2; mt++)
                #pragma unroll
                for (int nt = 0; nt < 8; nt++)
                    mma_f16(sacc[mt][nt], qa[mt][ks], kb[nt]);
        }

        // ---- masked online softmax (per row: quad shfl reductions) ----
        #pragma unroll
        for (int mt = 0; mt < 2; mt++) {
            #pragma unroll
            for (int p = 0; p < 2; p++) {
                const int qi_r = (w * 32 + mt * 16 + g + 8 * p) & 63;
                float mx = SMASK;
                #pragma unroll
                for (int nt = 0; nt < 8; nt++) {
                    int jt = chunk * 64 + nt * 8 + 2 * t4;
                    float s0 = sacc[mt][nt][2 * p];
                    float s1 = sacc[mt][nt][2 * p + 1];
                    bool v0 = (jt     >= qi_r) && (jt     <= qi_r + 127) && (j0 + jt     >= 0);
                    bool v1 = (jt + 1 >= qi_r) && (jt + 1 <= qi_r + 127) && (j0 + jt + 1 >= 0);
                    s0 = v0 ? s0 * SM_SCALE : SMASK;
                    s1 = v1 ? s1 * SM_SCALE : SMASK;
                    sacc[mt][nt][2 * p]     = s0;
                    sacc[mt][nt][2 * p + 1] = s1;
                    mx = fmaxf(mx, fmaxf(s0, s1));
                }
                mx = fmaxf(mx, __shfl_xor_sync(0xffffffffu, mx, 1));
                mx = fmaxf(mx, __shfl_xor_sync(0xffffffffu, mx, 2));
                float newm = fmaxf(mrow[mt][p], mx);
                float corr = __expf(mrow[mt][p] - newm);
                mrow[mt][p] = newm;
                float rs = 0.f;
                #pragma unroll
                for (int nt = 0; nt < 8; nt++) {
                    float e0 = __expf(sacc[mt][nt][2 * p]     - newm);
                    float e1 = __expf(sacc[mt][nt][2 * p + 1] - newm);
                    sacc[mt][nt][2 * p]     = e0;
                    sacc[mt][nt][2 * p + 1] = e1;
                    rs += e0 + e1;
                    oacc[mt][nt][2 * p]     *= corr;
                    oacc[mt][nt][2 * p + 1] *= corr;
                }
                rs += __shfl_xor_sync(0xffffffffu, rs, 1);
                rs += __shfl_xor_sync(0xffffffffu, rs, 2);
                lrow[mt][p] = lrow[mt][p] * corr + rs;
            }
        }

        // ---- O += P @ V ----
        #pragma unroll
        for (int ksP = 0; ksP < 4; ksP++) {
            uint32_t vb[8][2];
            #pragma unroll
            for (int np = 0; np < 4; np++) {
                int krow = chunk * 64 + ksP * 16 + rsel;
                int colb = np * 16 + hsel * 8;
                uint32_t r0, r1, r2, r3;
                ldsm_x4_trans(r0, r1, r2, r3, Vs + swz((uint32_t)(krow * 128 + colb * 2)));
                vb[2 * np][0] = r0; vb[2 * np][1] = r1;
                vb[2 * np + 1][0] = r2; vb[2 * np + 1][1] = r3;
            }
            uint32_t pa[2][4];
            #pragma unroll
            for (int mt = 0; mt < 2; mt++) {
                pa[mt][0] = packh2(sacc[mt][2 * ksP][0],     sacc[mt][2 * ksP][1]);
                pa[mt][1] = packh2(sacc[mt][2 * ksP][2],     sacc[mt][2 * ksP][3]);
                pa[mt][2] = packh2(sacc[mt][2 * ksP + 1][0], sacc[mt][2 * ksP + 1][1]);
                pa[mt][3] = packh2(sacc[mt][2 * ksP + 1][2], sacc[mt][2 * ksP + 1][3]);
            }
            #pragma unroll
            for (int mt = 0; mt < 2; mt++)
                #pragma unroll
                for (int nt = 0; nt < 8; nt++)
                    mma_f16(oacc[mt][nt], pa[mt], vb[nt]);
        }
    }

    // ---- epilogue: sink in denominator, write fp16 ----
    const int qh_w = w >> 1;                 // head constant per warp
    const int h = kv * QMULT + qh_w;
    const float snk = sinks[h];
    #pragma unroll
    for (int mt = 0; mt < 2; mt++) {
        #pragma unroll
        for (int p = 0; p < 2; p++) {
            int r = w * 32 + mt * 16 + g + 8 * p;
            int qi_r = r & 63;
            int itok = qstart + qi_r;
            float denom = lrow[mt][p] + __expf(snk - mrow[mt][p]);
            float inv = 1.0f / denom;
            __half* op = out + (size_t)(b * T_ + itok) * DM + h * 64;
            #pragma unroll
            for (int nt = 0; nt < 8; nt++) {
                int col = nt * 8 + 2 * t4;
                __half2 hv = __floats2half2_rn(oacc[mt][nt][2 * p] * inv,
                                               oacc[mt][nt][2 * p + 1] * inv);
                *(__half2*)(op + col) = hv;
            }
        }
    }
}

// ---------------- launch ----------------
extern "C" void kernel_launch(void* const* d_in, const int* in_sizes, int n_in,
                              void* d_out, int out_size) {
    const float* x      = (const float*)d_in[0];
    const float* qkv_w  = (const float*)d_in[1];
    const float* qkv_b  = (const float*)d_in[2];
    const float* out_w  = (const float*)d_in[3];
    const float* out_b  = (const float*)d_in[4];
    const float* sinks  = (const float*)d_in[5];
    float* out = (float*)d_out;

    float *qkv, *cosp, *sinp;
    __half *xh, *qwh, *owh, *attnh;
    cudaGetSymbolAddress((void**)&qkv,   g_qkv);
    cudaGetSymbolAddress((void**)&xh,    g_xh);
    cudaGetSymbolAddress((void**)&qwh,   g_qwh);
    cudaGetSymbolAddress((void**)&owh,   g_owh);
    cudaGetSymbolAddress((void**)&attnh, g_attnh);
    cudaGetSymbolAddress((void**)&cosp,  g_cos);
    cudaGetSymbolAddress((void**)&sinp,  g_sin);

    const int gemmSmem = NSTAGE * STAGE_BYTES + 1024;   // 197632
    cudaFuncSetAttribute(gemm_f16_nt_bias, cudaFuncAttributeMaxDynamicSharedMemorySize, gemmSmem);
    cudaFuncSetAttribute(attn_mma_kernel, cudaFuncAttributeMaxDynamicSharedMemorySize, ATTN_SMEM);

    // 1. rope tables
    rope_table_kernel<<<T_, 32>>>(cosp, sinp);

    // 2. fused fp16 conversion pass (x, qkv_w, out_w)
    {
        int total = N4X + N4Q + N4O;
        f16_convert_all_kernel<<<(total + 255) / 256, 256>>>(x, xh, qkv_w, qwh, out_w, owh);
    }

    // 3. QKV projection: [4096,3072] = x @ qkv_w^T + b   (fp16 mma)
    {
        dim3 grid(QKVD / BN, NTOK / BM);   // (12, 32)
        gemm_f16_nt_bias<<<grid, 256, gemmSmem>>>(xh, qwh, qkv_b, qkv, NTOK, QKVD, DM);
    }

    // 4. MMA flash attention with fused rope (fp16 output)
    {
        dim3 grid(T_ / 64, NKV, B_);
        attn_mma_kernel<<<grid, 256, ATTN_SMEM>>>(qkv, sinks, cosp, sinp, attnh);
    }

    // 5. output projection: [4096,2048] = attn @ out_w^T + b  (fp16 mma)
    {
        dim3 grid(DM / BN, NTOK / BM);     // (8, 32)
        gemm_f16_nt_bias<<<grid, 256, gemmSmem>>>(attnh, owh, out_b, out, NTOK, DM, DM);
    }
}

// round 17
// speedup vs baseline: 1.8456x; 1.0877x over previous
#include <cuda_runtime.h>
#include <cuda_fp16.h>
#include <math.h>
#include <math_constants.h>
#include <stdint.h>

// ---------------- problem constants ----------------
#define B_    4
#define T_    1024
#define DM    2048
#define HD    64
#define NH    32
#define NKV   8
#define QMULT 4
#define WIN   128
#define QKVD  3072           // 64*(32+16)
#define SM_SCALE 0.125f      // 1/sqrt(64)
#define NTOK  (B_*T_)        // 4096
#define SMASK (-1e30f)

// ---------------- scratch (no allocs allowed) ----------------
__device__ __half g_qkvh [NTOK * QKVD];  // 25.2 MB  roped qkv (fp16)
__device__ __half g_xh   [NTOK * DM];    // 16.8 MB  x -> fp16
__device__ __half g_qwh  [QKVD * DM];    // 12.6 MB  qkv_w -> fp16
__device__ __half g_owh  [DM * DM];      //  8.4 MB  out_w -> fp16
__device__ __half g_attnh[NTOK * DM];    // 16.8 MB  attn output (fp16)
__device__ float  g_cos  [T_ * 32];
__device__ float  g_sin  [T_ * 32];

// ---------------- PTX helpers ----------------
__device__ __forceinline__ uint32_t smem_u32(const void* p) {
    uint32_t a;
    asm("{ .reg .u64 t; cvta.to.shared.u64 t, %1; cvt.u32.u64 %0, t; }" : "=r"(a) : "l"(p));
    return a;
}
__device__ __forceinline__ void cp16(uint32_t dst, const void* src) {
    asm volatile("cp.async.cg.shared.global [%0], [%1], 16;" :: "r"(dst), "l"(src));
}
__device__ __forceinline__ void ldsm_x4(uint32_t& r0, uint32_t& r1, uint32_t& r2, uint32_t& r3, uint32_t addr) {
    asm volatile("ldmatrix.sync.aligned.m8n8.x4.shared.b16 {%0,%1,%2,%3}, [%4];"
        : "=r"(r0), "=r"(r1), "=r"(r2), "=r"(r3) : "r"(addr));
}
__device__ __forceinline__ void ldsm_x4_trans(uint32_t& r0, uint32_t& r1, uint32_t& r2, uint32_t& r3, uint32_t addr) {
    asm volatile("ldmatrix.sync.aligned.m8n8.x4.trans.shared.b16 {%0,%1,%2,%3}, [%4];"
        : "=r"(r0), "=r"(r1), "=r"(r2), "=r"(r3) : "r"(addr));
}
__device__ __forceinline__ void mma_f16(float* c, const uint32_t* a, const uint32_t* b) {
    asm volatile("mma.sync.aligned.m16n8k16.row.col.f32.f16.f16.f32 "
        "{%0,%1,%2,%3}, {%4,%5,%6,%7}, {%8,%9}, {%0,%1,%2,%3};"
        : "+f"(c[0]), "+f"(c[1]), "+f"(c[2]), "+f"(c[3])
        : "r"(a[0]), "r"(a[1]), "r"(a[2]), "r"(a[3]), "r"(b[0]), "r"(b[1]));
}
__device__ __forceinline__ uint32_t packh2(float a, float b) {
    __half2 h = __floats2half2_rn(a, b);
    return *(uint32_t*)&h;
}
__device__ __forceinline__ uint32_t swz(uint32_t off) { return off ^ ((off >> 3) & 0x70); }

// ---------------- rope tables (YaRN / NTK-by-parts) ----------------
__global__ void rope_table_kernel(float* __restrict__ cost, float* __restrict__ sint) {
    int t = blockIdx.x;
    int d = threadIdx.x;
    const double theta = 150000.0;
    const double two_pi = 6.283185307179586476925286766559;
    double freq = pow(theta, (double)d / 32.0);
    double concentration = 0.1 * log(32.0) + 1.0;
    double lt = log(theta);
    double low  = 32.0 * log(1024.0 / (32.0 * two_pi)) / lt;
    double high = 32.0 * log(1024.0 / (1.0  * two_pi)) / lt;
    double interpolation = 1.0 / (32.0 * freq);
    double extrapolation = 1.0 / freq;
    double ramp = ((double)d - low) / (high - low);
    ramp = fmin(fmax(ramp, 0.0), 1.0);
    double inv_freq = interpolation * ramp + extrapolation * (1.0 - ramp);
    double a = (double)t * inv_freq;
    cost[t * 32 + d] = (float)(cos(a) * concentration);
    sint[t * 32 + d] = (float)(sin(a) * concentration);
}

// ---------------- fused fp32 -> fp16 conversion (x, qkv_w, out_w in one grid) ----------------
#define N4X (NTOK * DM / 4)      // 2097152
#define N4Q (QKVD * DM / 4)      // 1572864
#define N4O (DM * DM / 4)        // 1048576
__global__ void f16_convert_all_kernel(const float* __restrict__ x, __half* __restrict__ xh,
                                       const float* __restrict__ qw, __half* __restrict__ qwh,
                                       const float* __restrict__ ow, __half* __restrict__ owh) {
    int i = blockIdx.x * blockDim.x + threadIdx.x;
    const float* in; __half* out; int k;
    if (i < N4X)                { in = x;  out = xh;  k = i; }
    else if (i < N4X + N4Q)     { in = qw; out = qwh; k = i - N4X; }
    else if (i < N4X + N4Q + N4O) { in = ow; out = owh; k = i - N4X - N4Q; }
    else return;
    float4 v = ((const float4*)in)[k];
    __half2* o2 = (__half2*)out;
    o2[2 * k]     = __floats2half2_rn(v.x, v.y);
    o2[2 * k + 1] = __floats2half2_rn(v.z, v.w);
}

// ---------------- GEMM mainloop config (R10 — measured best, unchanged) ----------------
#define BM 128
#define BN 256
#define BK 64
#define A_STAGE 16384
#define B_STAGE 32768
#define STAGE_BYTES (A_STAGE + B_STAGE)
#define NSTAGE 4

// mainloop as a macro-free pattern is duplicated in both GEMM kernels below.

// ---------------- out-projection GEMM: C fp32 = A @ B^T + bias ----------------
__global__ __launch_bounds__(256, 1) void gemm_f16_nt_bias(
    const __half* __restrict__ A, const __half* __restrict__ Bw,
    const float* __restrict__ bias, float* __restrict__ C,
    int M, int N, int K)
{
    extern __shared__ char dsm[];
    const uint32_t dynbase = smem_u32(dsm);
    const uint32_t base    = (dynbase + 1023u) & ~1023u;

    const int tid  = threadIdx.x;
    const int lane = tid & 31;
    const int wid  = tid >> 5;
    const int wm   = wid >> 2;
    const int wn   = wid & 3;
    const int bm   = blockIdx.y * BM;
    const int bn   = blockIdx.x * BN;

    float acc[4][8][4];
    #pragma unroll
    for (int i = 0; i < 4; i++)
        #pragma unroll
        for (int j = 0; j < 8; j++)
            #pragma unroll
            for (int r = 0; r < 4; r++) acc[i][j][r] = 0.0f;

    const int kIter = K / BK;

    auto load_stage = [&](int buf, int t) {
        const uint32_t aS = base + buf * STAGE_BYTES;
        const uint32_t bS = aS + A_STAGE;
        const __half* Ab = A  + (size_t)bm * K + (size_t)t * BK;
        const __half* Bb = Bw + (size_t)bn * K + (size_t)t * BK;
        #pragma unroll
        for (int j = 0; j < 4; j++) {
            int f = tid + 256 * j;
            int r = f >> 3, c = f & 7;
            cp16(aS + swz((uint32_t)(r * 128 + c * 16)), Ab + (size_t)r * K + c * 8);
        }
        #pragma unroll
        for (int j = 0; j < 8; j++) {
            int f = tid + 256 * j;
            int r = f >> 3, c = f & 7;
            cp16(bS + swz((uint32_t)(r * 128 + c * 16)), Bb + (size_t)r * K + c * 8);
        }
    };

    load_stage(0, 0);
    asm volatile("cp.async.commit_group;");
    load_stage(1, 1);
    asm volatile("cp.async.commit_group;");
    load_stage(2, 2);
    asm volatile("cp.async.commit_group;");

    const int rsel = lane & 15;
    const int hsel = (lane >> 4) & 1;

    uint32_t af[2][4][4];
    uint32_t bf[2][8][2];

    auto load_frags = [&](uint32_t aS, uint32_t bS, int ks,
                          uint32_t (&a)[4][4], uint32_t (&b)[8][2]) {
        #pragma unroll
        for (int mt = 0; mt < 4; mt++) {
            int row = wm * 64 + mt * 16 + rsel;
            ldsm_x4(a[mt][0], a[mt][1], a[mt][2], a[mt][3],
                    aS + swz((uint32_t)(row * 128 + ks * 32 + hsel * 16)));
        }
        #pragma unroll
        for (int np = 0; np < 4; np++) {
            int row = wn * 64 + np * 16 + rsel;
            uint32_t q0, q1, q2, q3;
            ldsm_x4(q0, q1, q2, q3, bS + swz((uint32_t)(row * 128 + ks * 32 + hsel * 16)));
            b[2 * np][0]     = q0; b[2 * np][1]     = q2;
            b[2 * np + 1][0] = q1; b[2 * np + 1][1] = q3;
        }
    };

    for (int t = 0; t < kIter; t++) {
        asm volatile("cp.async.wait_group 2;");
        __syncthreads();

        const uint32_t aS = base + (t & 3) * STAGE_BYTES;
        const uint32_t bS = aS + A_STAGE;

        load_frags(aS, bS, 0, af[0], bf[0]);

        if (t + 3 < kIter) load_stage((t + 3) & 3, t + 3);
        asm volatile("cp.async.commit_group;");

        #pragma unroll
        for (int ks = 0; ks < 4; ks++) {
            const int cur = ks & 1;
            if (ks < 3) load_frags(aS, bS, ks + 1, af[cur ^ 1], bf[cur ^ 1]);
            #pragma unroll
            for (int mt = 0; mt < 4; mt++)
                #pragma unroll
                for (int nt = 0; nt < 8; nt++)
                    mma_f16(acc[mt][nt], af[cur][mt], bf[cur][nt]);
        }
    }

    const int cx = (lane & 3) * 2;
    const int cy = lane >> 2;
    #pragma unroll
    for (int nt = 0; nt < 8; nt++) {
        const int c0 = bn + wn * 64 + nt * 8 + cx;
        const float bv0 = bias[c0];
        const float bv1 = bias[c0 + 1];
        #pragma unroll
        for (int mt = 0; mt < 4; mt++) {
            const int r0 = bm + wm * 64 + mt * 16 + cy;
            *(float2*)(C + (size_t)r0 * N + c0)       = make_float2(acc[mt][nt][0] + bv0, acc[mt][nt][1] + bv1);
            *(float2*)(C + (size_t)(r0 + 8) * N + c0) = make_float2(acc[mt][nt][2] + bv0, acc[mt][nt][3] + bv1);
        }
    }
}

// ---------------- QKV GEMM with fused bias+RoPE epilogue, fp16 output ----------------
// Warp tile (64 cols) == one head; rope pairs (d, d+32) live in fragments (nt, nt+4).
__global__ __launch_bounds__(256, 1) void gemm_qkv_rope(
    const __half* __restrict__ A, const __half* __restrict__ Bw,
    const float* __restrict__ bias,
    const float* __restrict__ cost, const float* __restrict__ sint,
    __half* __restrict__ C,
    int M, int N, int K)
{
    extern __shared__ char dsm[];
    const uint32_t dynbase = smem_u32(dsm);
    const uint32_t base    = (dynbase + 1023u) & ~1023u;

    const int tid  = threadIdx.x;
    const int lane = tid & 31;
    const int wid  = tid >> 5;
    const int wm   = wid >> 2;
    const int wn   = wid & 3;
    const int bm   = blockIdx.y * BM;
    const int bn   = blockIdx.x * BN;

    float acc[4][8][4];
    #pragma unroll
    for (int i = 0; i < 4; i++)
        #pragma unroll
        for (int j = 0; j < 8; j++)
            #pragma unroll
            for (int r = 0; r < 4; r++) acc[i][j][r] = 0.0f;

    const int kIter = K / BK;

    auto load_stage = [&](int buf, int t) {
        const uint32_t aS = base + buf * STAGE_BYTES;
        const uint32_t bS = aS + A_STAGE;
        const __half* Ab = A  + (size_t)bm * K + (size_t)t * BK;
        const __half* Bb = Bw + (size_t)bn * K + (size_t)t * BK;
        #pragma unroll
        for (int j = 0; j < 4; j++) {
            int f = tid + 256 * j;
            int r = f >> 3, c = f & 7;
            cp16(aS + swz((uint32_t)(r * 128 + c * 16)), Ab + (size_t)r * K + c * 8);
        }
        #pragma unroll
        for (int j = 0; j < 8; j++) {
            int f = tid + 256 * j;
            int r = f >> 3, c = f & 7;
            cp16(bS + swz((uint32_t)(r * 128 + c * 16)), Bb + (size_t)r * K + c * 8);
        }
    };

    load_stage(0, 0);
    asm volatile("cp.async.commit_group;");
    load_stage(1, 1);
    asm volatile("cp.async.commit_group;");
    load_stage(2, 2);
    asm volatile("cp.async.commit_group;");

    const int rsel = lane & 15;
    const int hsel = (lane >> 4) & 1;

    uint32_t af[2][4][4];
    uint32_t bf[2][8][2];

    auto load_frags = [&](uint32_t aS, uint32_t bS, int ks,
                          uint32_t (&a)[4][4], uint32_t (&b)[8][2]) {
        #pragma unroll
        for (int mt = 0; mt < 4; mt++) {
            int row = wm * 64 + mt * 16 + rsel;
            ldsm_x4(a[mt][0], a[mt][1], a[mt][2], a[mt][3],
                    aS + swz((uint32_t)(row * 128 + ks * 32 + hsel * 16)));
        }
        #pragma unroll
        for (int np = 0; np < 4; np++) {
            int row = wn * 64 + np * 16 + rsel;
            uint32_t q0, q1, q2, q3;
            ldsm_x4(q0, q1, q2, q3, bS + swz((uint32_t)(row * 128 + ks * 32 + hsel * 16)));
            b[2 * np][0]     = q0; b[2 * np][1]     = q2;
            b[2 * np + 1][0] = q1; b[2 * np + 1][1] = q3;
        }
    };

    for (int t = 0; t < kIter; t++) {
        asm volatile("cp.async.wait_group 2;");
        __syncthreads();

        const uint32_t aS = base + (t & 3) * STAGE_BYTES;
        const uint32_t bS = aS + A_STAGE;

        load_frags(aS, bS, 0, af[0], bf[0]);

        if (t + 3 < kIter) load_stage((t + 3) & 3, t + 3);
        asm volatile("cp.async.commit_group;");

        #pragma unroll
        for (int ks = 0; ks < 4; ks++) {
            const int cur = ks & 1;
            if (ks < 3) load_frags(aS, bS, ks + 1, af[cur ^ 1], bf[cur ^ 1]);
            #pragma unroll
            for (int mt = 0; mt < 4; mt++)
                #pragma unroll
                for (int nt = 0; nt < 8; nt++)
                    mma_f16(acc[mt][nt], af[cur][mt], bf[cur][nt]);
        }
    }

    // ---- epilogue: bias + rope (heads < 40) -> fp16 ----
    const int cx = (lane & 3) * 2;
    const int cy = lane >> 2;
    const int col0 = bn + wn * 64;        // 64-aligned -> one head per warp tile
    const bool dorope = (col0 >> 6) < 40; // q heads 0..31, k heads 32..39, v heads 40..47
    #pragma unroll
    for (int mt = 0; mt < 4; mt++) {
        #pragma unroll
        for (int p = 0; p < 2; p++) {
            const int row = bm + wm * 64 + mt * 16 + cy + p * 8;
            const int t = row & (T_ - 1);
            __half* crow = C + (size_t)row * N + col0;
            if (dorope) {
                #pragma unroll
                for (int nt = 0; nt < 4; nt++) {
                    const int d = nt * 8 + cx;
                    float x1a = acc[mt][nt][2 * p]         + bias[col0 + d];
                    float x1b = acc[mt][nt][2 * p + 1]     + bias[col0 + d + 1];
                    float x2a = acc[mt][nt + 4][2 * p]     + bias[col0 + d + 32];
                    float x2b = acc[mt][nt + 4][2 * p + 1] + bias[col0 + d + 33];
                    float2 cc = *(const float2*)(cost + t * 32 + d);
                    float2 ss = *(const float2*)(sint + t * 32 + d);
                    *(__half2*)(crow + d)      = __floats2half2_rn(x1a * cc.x - x2a * ss.x,
                                                                   x1b * cc.y - x2b * ss.y);
                    *(__half2*)(crow + d + 32) = __floats2half2_rn(x2a * cc.x + x1a * ss.x,
                                                                   x2b * cc.y + x1b * ss.y);
                }
            } else {
                #pragma unroll
                for (int nt = 0; nt < 8; nt++) {
                    const int d = nt * 8 + cx;
                    *(__half2*)(crow + d) = __floats2half2_rn(acc[mt][nt][2 * p]     + bias[col0 + d],
                                                              acc[mt][nt][2 * p + 1] + bias[col0 + d + 1]);
                }
            }
        }
    }
}

// ---------------- MMA flash attention (inputs pre-roped fp16) ----------------
// grid (T/64, NKV, B), 256 threads = 8 warps; cp.async tile loads.
#define QS_OFF 0
#define KS_OFF 32768
#define VS_OFF 57344
#define ATTN_SMEM 81920

__global__ __launch_bounds__(256, 1) void attn_mma_kernel(
    const __half* __restrict__ qkvh, const float* __restrict__ sinks,
    __half* __restrict__ out)
{
    extern __shared__ char smraw[];
    const uint32_t sbase = smem_u32(smraw);
    const uint32_t Qs = sbase + QS_OFF;
    const uint32_t Ks = sbase + KS_OFF;
    const uint32_t Vs = sbase + VS_OFF;

    const int qb = blockIdx.x;
    const int kv = blockIdx.y;
    const int b  = blockIdx.z;
    const int tid = threadIdx.x;
    const int lane = tid & 31;
    const int w    = tid >> 5;
    const int g    = lane >> 2;
    const int t4   = lane & 3;
    const int rsel = lane & 15;
    const int hsel = lane >> 4;

    const int qstart = qb * 64;
    const int j0 = qstart - (WIN - 1);

    // ---- Q smem: 256 rows x 128B, direct cp.async ----
    for (int idx = tid; idx < 256 * 8; idx += 256) {
        int r = idx >> 3, c = idx & 7;
        int qh = r >> 6, qi2 = r & 63;
        const __half* src = qkvh + (size_t)(b * T_ + qstart + qi2) * QKVD
                          + (kv * QMULT + qh) * 64 + c * 8;
        cp16(Qs + swz((uint32_t)(r * 128 + c * 16)), src);
    }
    // ---- K smem: 192 rows x 128B ----
    for (int idx = tid; idx < 192 * 8; idx += 256) {
        int row = idx >> 3, c = idx & 7;
        int j = j0 + row;
        uint32_t off = (uint32_t)(KS_OFF + swz((uint32_t)(row * 128 + c * 16)));
        if (j >= 0 && j < T_)
            cp16(sbase + off, qkvh + (size_t)(b * T_ + j) * QKVD + 2048 + kv * 64 + c * 8);
        else
            *(uint4*)(smraw + off) = make_uint4(0, 0, 0, 0);
    }
    // ---- V smem: 192 rows x 128B ----
    for (int idx = tid; idx < 192 * 8; idx += 256) {
        int row = idx >> 3, c = idx & 7;
        int j = j0 + row;
        uint32_t off = (uint32_t)(VS_OFF + swz((uint32_t)(row * 128 + c * 16)));
        if (j >= 0 && j < T_)
            cp16(sbase + off, qkvh + (size_t)(b * T_ + j) * QKVD + 2560 + kv * 64 + c * 8);
        else
            *(uint4*)(smraw + off) = make_uint4(0, 0, 0, 0);
    }
    asm volatile("cp.async.commit_group;");
    asm volatile("cp.async.wait_group 0;");
    __syncthreads();

    // ---- resident Q fragments: warp rows [w*32, w*32+32) ----
    uint32_t qa[2][4][4];
    #pragma unroll
    for (int mt = 0; mt < 2; mt++)
        #pragma unroll
        for (int ks = 0; ks < 4; ks++) {
            int row = w * 32 + mt * 16 + rsel;
            ldsm_x4(qa[mt][ks][0], qa[mt][ks][1], qa[mt][ks][2], qa[mt][ks][3],
                    Qs + swz((uint32_t)(row * 128 + ks * 32 + hsel * 16)));
        }

    float oacc[2][8][4];
    #pragma unroll
    for (int mt = 0; mt < 2; mt++)
        #pragma unroll
        for (int nt = 0; nt < 8; nt++)
            #pragma unroll
            for (int c = 0; c < 4; c++) oacc[mt][nt][c] = 0.0f;
    float mrow[2][2] = {{SMASK, SMASK}, {SMASK, SMASK}};
    float lrow[2][2] = {{0.f, 0.f}, {0.f, 0.f}};

    #pragma unroll
    for (int chunk = 0; chunk < 3; chunk++) {
        float sacc[2][8][4];
        #pragma unroll
        for (int mt = 0; mt < 2; mt++)
            #pragma unroll
            for (int nt = 0; nt < 8; nt++)
                #pragma unroll
                for (int c = 0; c < 4; c++) sacc[mt][nt][c] = 0.0f;

        #pragma unroll
        for (int ks = 0; ks < 4; ks++) {
            uint32_t kb[8][2];
            #pragma unroll
            for (int np = 0; np < 4; np++) {
                int row = chunk * 64 + np * 16 + rsel;
                uint32_t q0, q1, q2, q3;
                ldsm_x4(q0, q1, q2, q3, Ks + swz((uint32_t)(row * 128 + ks * 32 + hsel * 16)));
                kb[2 * np][0] = q0; kb[2 * np][1] = q2;
                kb[2 * np + 1][0] = q1; kb[2 * np + 1][1] = q3;
            }
            #pragma unroll
            for (int mt = 0; mt < 2; mt++)
                #pragma unroll
                for (int nt = 0; nt < 8; nt++)
                    mma_f16(sacc[mt][nt], qa[mt][ks], kb[nt]);
        }

        // ---- masked online softmax ----
        #pragma unroll
        for (int mt = 0; mt < 2; mt++) {
            #pragma unroll
            for (int p = 0; p < 2; p++) {
                const int qi_r = (w * 32 + mt * 16 + g + 8 * p) & 63;
                float mx = SMASK;
                #pragma unroll
                for (int nt = 0; nt < 8; nt++) {
                    int jt = chunk * 64 + nt * 8 + 2 * t4;
                    float s0 = sacc[mt][nt][2 * p];
                    float s1 = sacc[mt][nt][2 * p + 1];
                    bool v0 = (jt     >= qi_r) && (jt     <= qi_r + 127) && (j0 + jt     >= 0);
                    bool v1 = (jt + 1 >= qi_r) && (jt + 1 <= qi_r + 127) && (j0 + jt + 1 >= 0);
                    s0 = v0 ? s0 * SM_SCALE : SMASK;
                    s1 = v1 ? s1 * SM_SCALE : SMASK;
                    sacc[mt][nt][2 * p]     = s0;
                    sacc[mt][nt][2 * p + 1] = s1;
                    mx = fmaxf(mx, fmaxf(s0, s1));
                }
                mx = fmaxf(mx, __shfl_xor_sync(0xffffffffu, mx, 1));
                mx = fmaxf(mx, __shfl_xor_sync(0xffffffffu, mx, 2));
                float newm = fmaxf(mrow[mt][p], mx);
                float corr = __expf(mrow[mt][p] - newm);
                mrow[mt][p] = newm;
                float rs = 0.f;
                #pragma unroll
                for (int nt = 0; nt < 8; nt++) {
                    float e0 = __expf(sacc[mt][nt][2 * p]     - newm);
                    float e1 = __expf(sacc[mt][nt][2 * p + 1] - newm);
                    sacc[mt][nt][2 * p]     = e0;
                    sacc[mt][nt][2 * p + 1] = e1;
                    rs += e0 + e1;
                    oacc[mt][nt][2 * p]     *= corr;
                    oacc[mt][nt][2 * p + 1] *= corr;
                }
                rs += __shfl_xor_sync(0xffffffffu, rs, 1);
                rs += __shfl_xor_sync(0xffffffffu, rs, 2);
                lrow[mt][p] = lrow[mt][p] * corr + rs;
            }
        }

        // ---- O += P @ V ----
        #pragma unroll
        for (int ksP = 0; ksP < 4; ksP++) {
            uint32_t vb[8][2];
            #pragma unroll
            for (int np = 0; np < 4; np++) {
                int krow = chunk * 64 + ksP * 16 + rsel;
                int colb = np * 16 + hsel * 8;
                uint32_t r0, r1, r2, r3;
                ldsm_x4_trans(r0, r1, r2, r3, Vs + swz((uint32_t)(krow * 128 + colb * 2)));
                vb[2 * np][0] = r0; vb[2 * np][1] = r1;
                vb[2 * np + 1][0] = r2; vb[2 * np + 1][1] = r3;
            }
            uint32_t pa[2][4];
            #pragma unroll
            for (int mt = 0; mt < 2; mt++) {
                pa[mt][0] = packh2(sacc[mt][2 * ksP][0],     sacc[mt][2 * ksP][1]);
                pa[mt][1] = packh2(sacc[mt][2 * ksP][2],     sacc[mt][2 * ksP][3]);
                pa[mt][2] = packh2(sacc[mt][2 * ksP + 1][0], sacc[mt][2 * ksP + 1][1]);
                pa[mt][3] = packh2(sacc[mt][2 * ksP + 1][2], sacc[mt][2 * ksP + 1][3]);
            }
            #pragma unroll
            for (int mt = 0; mt < 2; mt++)
                #pragma unroll
                for (int nt = 0; nt < 8; nt++)
                    mma_f16(oacc[mt][nt], pa[mt], vb[nt]);
        }
    }

    // ---- epilogue ----
    const int qh_w = w >> 1;
    const int h = kv * QMULT + qh_w;
    const float snk = sinks[h];
    #pragma unroll
    for (int mt = 0; mt < 2; mt++) {
        #pragma unroll
        for (int p = 0; p < 2; p++) {
            int r = w * 32 + mt * 16 + g + 8 * p;
            int qi_r = r & 63;
            int itok = qstart + qi_r;
            float denom = lrow[mt][p] + __expf(snk - mrow[mt][p]);
            float inv = 1.0f / denom;
            __half* op = out + (size_t)(b * T_ + itok) * DM + h * 64;
            #pragma unroll
            for (int nt = 0; nt < 8; nt++) {
                int col = nt * 8 + 2 * t4;
                __half2 hv = __floats2half2_rn(oacc[mt][nt][2 * p] * inv,
                                               oacc[mt][nt][2 * p + 1] * inv);
                *(__half2*)(op + col) = hv;
            }
        }
    }
}

// ---------------- launch ----------------
extern "C" void kernel_launch(void* const* d_in, const int* in_sizes, int n_in,
                              void* d_out, int out_size) {
    const float* x      = (const float*)d_in[0];
    const float* qkv_w  = (const float*)d_in[1];
    const float* qkv_b  = (const float*)d_in[2];
    const float* out_w  = (const float*)d_in[3];
    const float* out_b  = (const float*)d_in[4];
    const float* sinks  = (const float*)d_in[5];
    float* out = (float*)d_out;

    float *cosp, *sinp;
    __half *qkvh, *xh, *qwh, *owh, *attnh;
    cudaGetSymbolAddress((void**)&qkvh,  g_qkvh);
    cudaGetSymbolAddress((void**)&xh,    g_xh);
    cudaGetSymbolAddress((void**)&qwh,   g_qwh);
    cudaGetSymbolAddress((void**)&owh,   g_owh);
    cudaGetSymbolAddress((void**)&attnh, g_attnh);
    cudaGetSymbolAddress((void**)&cosp,  g_cos);
    cudaGetSymbolAddress((void**)&sinp,  g_sin);

    const int gemmSmem = NSTAGE * STAGE_BYTES + 1024;   // 197632
    cudaFuncSetAttribute(gemm_f16_nt_bias, cudaFuncAttributeMaxDynamicSharedMemorySize, gemmSmem);
    cudaFuncSetAttribute(gemm_qkv_rope,    cudaFuncAttributeMaxDynamicSharedMemorySize, gemmSmem);
    cudaFuncSetAttribute(attn_mma_kernel,  cudaFuncAttributeMaxDynamicSharedMemorySize, ATTN_SMEM);

    // 1. rope tables
    rope_table_kernel<<<T_, 32>>>(cosp, sinp);

    // 2. fused fp16 conversion pass (x, qkv_w, out_w)
    {
        int total = N4X + N4Q + N4O;
        f16_convert_all_kernel<<<(total + 255) / 256, 256>>>(x, xh, qkv_w, qwh, out_w, owh);
    }

    // 3. QKV projection + fused bias/rope, fp16 output
    {
        dim3 grid(QKVD / BN, NTOK / BM);   // (12, 32)
        gemm_qkv_rope<<<grid, 256, gemmSmem>>>(xh, qwh, qkv_b, cosp, sinp, qkvh, NTOK, QKVD, DM);
    }

    // 4. MMA flash attention (pre-roped fp16 inputs)
    {
        dim3 grid(T_ / 64, NKV, B_);
        attn_mma_kernel<<<grid, 256, ATTN_SMEM>>>(qkvh, sinks, attnh);
    }

    // 5. output projection: [4096,2048] = attn @ out_w^T + b  (fp16 mma, fp32 out)
    {
        dim3 grid(DM / BN, NTOK / BM);     // (8, 32)
        gemm_f16_nt_bias<<<grid, 256, gemmSmem>>>(attnh, owh, out_b, out, NTOK, DM, DM);
    }
}